// round 4
// baseline (speedup 1.0000x reference)
#include <cuda_runtime.h>
#include <stdint.h>

#define NPTS   262144
#define NLEV   16
#define TMASK  0x7FFFFu

// shared memory layout (float offsets)
#define O_DW1 0        // 32*64  = 2048
#define O_DB1 2048     // 64
#define O_DW2 2112     // 64*16  = 1024
#define O_DB2 3136     // 16
#define O_CW1 3152     // 32*64  = 2048
#define O_CB1 5200     // 64
#define O_CW2 5264     // 64*64  = 4096
#define O_CB2 9360     // 64
#define O_CW3 9424     // 64*64  = 4096
#define O_CB3 13520    // 64
#define O_CW4 13584    // 64*3   = 192
#define O_CB4 13776    // 3
#define SMEM_FLOATS 13780
#define SMEM_BYTES  (SMEM_FLOATS * 4)

__global__ void __launch_bounds__(128)
nerf_fused_kernel(const float*  __restrict__ coords,
                  const float*  __restrict__ dirs,
                  const float2* __restrict__ emb,
                  const float*  __restrict__ dw1, const float* __restrict__ db1,
                  const float*  __restrict__ dw2, const float* __restrict__ db2,
                  const float*  __restrict__ cw1, const float* __restrict__ cb1,
                  const float*  __restrict__ cw2, const float* __restrict__ cb2,
                  const float*  __restrict__ cw3, const float* __restrict__ cb3,
                  const float*  __restrict__ cw4, const float* __restrict__ cb4,
                  float* __restrict__ out)
{
    extern __shared__ float sm[];

    // ---- cooperative weight load into shared ----
    {
        const float* srcs[12] = {dw1, db1, dw2, db2, cw1, cb1, cw2, cb2, cw3, cb3, cw4, cb4};
        const int    offs[12] = {O_DW1, O_DB1, O_DW2, O_DB2, O_CW1, O_CB1,
                                 O_CW2, O_CB2, O_CW3, O_CB3, O_CW4, O_CB4};
        const int    cnts[12] = {2048, 64, 1024, 16, 2048, 64, 4096, 64, 4096, 64, 192, 3};
        for (int a = 0; a < 12; a++) {
            const float* s = srcs[a];
            int o = offs[a], c = cnts[a];
            for (int i = threadIdx.x; i < c; i += 128)
                sm[o + i] = s[i];
        }
    }
    __syncthreads();

    const int p = blockIdx.x * 128 + threadIdx.x;

    // ---------------- hash-grid encoding ----------------
    const float cx = coords[3 * p + 0];
    const float cy = coords[3 * p + 1];
    const float cz = coords[3 * p + 2];

    float feat[32];
    // floor(16 * (512/16)^(l/15)) — canonical instant-NGP per-level resolutions
    const float RESV[16] = {16.f, 20.f, 25.f, 32.f, 40.f, 50.f, 64.f, 80.f,
                            101.f, 128.f, 161.f, 203.f, 256.f, 322.f, 406.f, 512.f};

#pragma unroll
    for (int l = 0; l < NLEV; l++) {
        const float r = RESV[l];
        float fx = cx * r, fy = cy * r, fz = cz * r;
        float xf = floorf(fx), yf = floorf(fy), zf = floorf(fz);
        float tx = fx - xf, ty = fy - yf, tz = fz - zf;
        uint32_t px = (uint32_t)xf, py = (uint32_t)yf, pz = (uint32_t)zf;

        uint32_t hx0 = px;                  uint32_t hx1 = px + 1u;
        uint32_t hy0 = py * 2654435761u;    uint32_t hy1 = hy0 + 2654435761u;
        uint32_t hz0 = pz * 805459861u;     uint32_t hz1 = hz0 + 805459861u;

        const float2* t = emb + ((size_t)l << 19);
        float2 e000 = __ldg(t + ((hx0 ^ hy0 ^ hz0) & TMASK));
        float2 e001 = __ldg(t + ((hx0 ^ hy0 ^ hz1) & TMASK));
        float2 e010 = __ldg(t + ((hx0 ^ hy1 ^ hz0) & TMASK));
        float2 e011 = __ldg(t + ((hx0 ^ hy1 ^ hz1) & TMASK));
        float2 e100 = __ldg(t + ((hx1 ^ hy0 ^ hz0) & TMASK));
        float2 e101 = __ldg(t + ((hx1 ^ hy0 ^ hz1) & TMASK));
        float2 e110 = __ldg(t + ((hx1 ^ hy1 ^ hz0) & TMASK));
        float2 e111 = __ldg(t + ((hx1 ^ hy1 ^ hz1) & TMASK));

        float ux = 1.f - tx, uy = 1.f - ty, uz = 1.f - tz;
        float w000 = (ux * uy) * uz, w001 = (ux * uy) * tz;
        float w010 = (ux * ty) * uz, w011 = (ux * ty) * tz;
        float w100 = (tx * uy) * uz, w101 = (tx * uy) * tz;
        float w110 = (tx * ty) * uz, w111 = (tx * ty) * tz;

        float a0 = w000 * e000.x; float a1 = w000 * e000.y;
        a0 = fmaf(w001, e001.x, a0); a1 = fmaf(w001, e001.y, a1);
        a0 = fmaf(w010, e010.x, a0); a1 = fmaf(w010, e010.y, a1);
        a0 = fmaf(w011, e011.x, a0); a1 = fmaf(w011, e011.y, a1);
        a0 = fmaf(w100, e100.x, a0); a1 = fmaf(w100, e100.y, a1);
        a0 = fmaf(w101, e101.x, a0); a1 = fmaf(w101, e101.y, a1);
        a0 = fmaf(w110, e110.x, a0); a1 = fmaf(w110, e110.y, a1);
        a0 = fmaf(w111, e111.x, a0); a1 = fmaf(w111, e111.y, a1);

        feat[2 * l + 0] = a0;
        feat[2 * l + 1] = a1;
    }

    // ---------------- density MLP: 32 -> 64 (relu) ----------------
    float h[64];
#pragma unroll
    for (int j = 0; j < 64; j++) h[j] = sm[O_DB1 + j];
#pragma unroll
    for (int i = 0; i < 32; i++) {
        float f = feat[i];
#pragma unroll
        for (int j = 0; j < 64; j++)
            h[j] = fmaf(f, sm[O_DW1 + i * 64 + j], h[j]);
    }
#pragma unroll
    for (int j = 0; j < 64; j++) h[j] = fmaxf(h[j], 0.f);

    // ---------------- density MLP: 64 -> 16 ----------------
    float dout[16];
#pragma unroll
    for (int k = 0; k < 16; k++) dout[k] = sm[O_DB2 + k];
#pragma unroll
    for (int i = 0; i < 64; i++) {
        float f = h[i];
#pragma unroll
        for (int k = 0; k < 16; k++)
            dout[k] = fmaf(f, sm[O_DW2 + i * 16 + k], dout[k]);
    }

    const float density = expf(dout[0]);

    // ---------------- SH deg-4 encoding of normalized direction ----------------
    float dx = dirs[3 * p + 0];
    float dy = dirs[3 * p + 1];
    float dz = dirs[3 * p + 2];
    float nrm = sqrtf(dx * dx + dy * dy + dz * dz);
    dx /= nrm; dy /= nrm; dz /= nrm;
    // replicate reference's (d+1)/2 * 2 - 1 transform bit-for-bit-ish
    float x = ((dx + 1.f) * 0.5f) * 2.f - 1.f;
    float y = ((dy + 1.f) * 0.5f) * 2.f - 1.f;
    float z = ((dz + 1.f) * 0.5f) * 2.f - 1.f;

    float xx = x * x, yy = y * y, zz = z * z;
    float xy = x * y, yz = y * z, xz = x * z;

    float inp[32];
    inp[0]  = 0.28209479177387814f;
    inp[1]  = -0.48860251190291987f * y;
    inp[2]  =  0.48860251190291987f * z;
    inp[3]  = -0.48860251190291987f * x;
    inp[4]  =  1.0925484305920792f * xy;
    inp[5]  = -1.0925484305920792f * yz;
    inp[6]  =  0.94617469575756f * zz - 0.31539156525252f;
    inp[7]  = -1.0925484305920792f * xz;
    inp[8]  =  0.5462742152960396f * (xx - yy);
    inp[9]  =  0.5900435899266435f * y * (-3.0f * xx + yy);
    inp[10] =  2.890611442640554f * xy * z;
    inp[11] =  0.4570457994644657f * y * (1.0f - 5.0f * zz);
    inp[12] =  0.3731763325901154f * z * (5.0f * zz - 3.0f);
    inp[13] =  0.4570457994644657f * x * (1.0f - 5.0f * zz);
    inp[14] =  1.445305721320277f * z * (xx - yy);
    inp[15] =  0.5900435899266435f * x * (xx - 3.0f * yy);
#pragma unroll
    for (int k = 0; k < 16; k++) inp[16 + k] = dout[k];

    // ---------------- color MLP layer 1: 32 -> 64 (relu) ----------------
    float xa[64];
#pragma unroll
    for (int j = 0; j < 64; j++) xa[j] = sm[O_CB1 + j];
#pragma unroll
    for (int i = 0; i < 32; i++) {
        float f = inp[i];
#pragma unroll
        for (int j = 0; j < 64; j++)
            xa[j] = fmaf(f, sm[O_CW1 + i * 64 + j], xa[j]);
    }
#pragma unroll
    for (int j = 0; j < 64; j++) xa[j] = fmaxf(xa[j], 0.f);

    // ---------------- color MLP layer 2: 64 -> 64 (relu) ----------------
    float xb[64];
#pragma unroll
    for (int j = 0; j < 64; j++) xb[j] = sm[O_CB2 + j];
#pragma unroll
    for (int i = 0; i < 64; i++) {
        float f = xa[i];
#pragma unroll
        for (int j = 0; j < 64; j++)
            xb[j] = fmaf(f, sm[O_CW2 + i * 64 + j], xb[j]);
    }
#pragma unroll
    for (int j = 0; j < 64; j++) xb[j] = fmaxf(xb[j], 0.f);

    // ---------------- color MLP layer 3: 64 -> 64 (relu) ----------------
#pragma unroll
    for (int j = 0; j < 64; j++) xa[j] = sm[O_CB3 + j];
#pragma unroll
    for (int i = 0; i < 64; i++) {
        float f = xb[i];
#pragma unroll
        for (int j = 0; j < 64; j++)
            xa[j] = fmaf(f, sm[O_CW3 + i * 64 + j], xa[j]);
    }
#pragma unroll
    for (int j = 0; j < 64; j++) xa[j] = fmaxf(xa[j], 0.f);

    // ---------------- color MLP layer 4: 64 -> 3 (sigmoid) ----------------
    float c0 = sm[O_CB4 + 0], c1 = sm[O_CB4 + 1], c2 = sm[O_CB4 + 2];
#pragma unroll
    for (int i = 0; i < 64; i++) {
        float f = xa[i];
        c0 = fmaf(f, sm[O_CW4 + i * 3 + 0], c0);
        c1 = fmaf(f, sm[O_CW4 + i * 3 + 1], c1);
        c2 = fmaf(f, sm[O_CW4 + i * 3 + 2], c2);
    }
    c0 = 1.f / (1.f + expf(-c0));
    c1 = 1.f / (1.f + expf(-c1));
    c2 = 1.f / (1.f + expf(-c2));

    // ---------------- outputs: [density(B)] then [color(B,3)] ----------------
    out[p] = density;
    out[NPTS + 3 * p + 0] = c0;
    out[NPTS + 3 * p + 1] = c1;
    out[NPTS + 3 * p + 2] = c2;
}

extern "C" void kernel_launch(void* const* d_in, const int* in_sizes, int n_in,
                              void* d_out, int out_size)
{
    const float*  coords = (const float*)d_in[0];
    const float*  dirs   = (const float*)d_in[1];
    const float2* emb    = (const float2*)d_in[2];
    const float*  dw1 = (const float*)d_in[3];
    const float*  db1 = (const float*)d_in[4];
    const float*  dw2 = (const float*)d_in[5];
    const float*  db2 = (const float*)d_in[6];
    const float*  cw1 = (const float*)d_in[7];
    const float*  cb1 = (const float*)d_in[8];
    const float*  cw2 = (const float*)d_in[9];
    const float*  cb2 = (const float*)d_in[10];
    const float*  cw3 = (const float*)d_in[11];
    const float*  cb3 = (const float*)d_in[12];
    const float*  cw4 = (const float*)d_in[13];
    const float*  cb4 = (const float*)d_in[14];
    float* out = (float*)d_out;

    // 55,120 B dynamic smem > 48 KB static limit; set opt-in every call
    // (idempotent, deterministic, not a stream op -> capture-safe).
    cudaFuncSetAttribute(nerf_fused_kernel,
                         cudaFuncAttributeMaxDynamicSharedMemorySize, SMEM_BYTES);

    nerf_fused_kernel<<<NPTS / 128, 128, SMEM_BYTES>>>(
        coords, dirs, emb,
        dw1, db1, dw2, db2,
        cw1, cb1, cw2, cb2, cw3, cb3, cw4, cb4,
        out);
}

// round 5
// speedup vs baseline: 1.2400x; 1.2400x over previous
#include <cuda_runtime.h>
#include <stdint.h>

#define NPTS   262144
#define NLEV   16
#define TMASK  0x7FFFFu

// shared memory layout (float offsets) — all 16B aligned, rows 16B aligned
#define O_DW1 0        // 32*64  = 2048
#define O_DB1 2048     // 64
#define O_DW2 2112     // 64*16  = 1024
#define O_DB2 3136     // 16
#define O_CW1 3152     // 32*64  = 2048
#define O_CB1 5200     // 64
#define O_CW2 5264     // 64*64  = 4096
#define O_CB2 9360     // 64
#define O_CW3 9424     // 64*64  = 4096
#define O_CB3 13520    // 64
#define O_CW4 13584    // 64*3   = 192
#define O_CB4 13776    // 3
#define SMEM_FLOATS 13780
#define SMEM_BYTES  (SMEM_FLOATS * 4)

typedef unsigned long long u64;

// ---- packed f32x2 primitives (sm_100+; FFMA2 only reachable via PTX) ----
__device__ __forceinline__ u64 pk2(float a, float b) {
    u64 r; asm("mov.b64 %0,{%1,%2};" : "=l"(r) : "f"(a), "f"(b)); return r;
}
__device__ __forceinline__ float2 upk2(u64 v) {
    float2 f; asm("mov.b64 {%0,%1},%2;" : "=f"(f.x), "=f"(f.y) : "l"(v)); return f;
}
__device__ __forceinline__ u64 ffma2(u64 a, u64 b, u64 c) {
    u64 d; asm("fma.rn.f32x2 %0,%1,%2,%3;" : "=l"(d) : "l"(a), "l"(b), "l"(c)); return d;
}

// Packed dense layer: NIN scalar inputs (given as NIN/2 packed pairs),
// NOUT outputs accumulated as NOUT/2 packed pairs. Weights [NIN][NOUT]
// row-major in shared (pair-contiguous along NOUT).
template<int NIN, int NOUT>
__device__ __forceinline__ void layer_pk(const float* __restrict__ wsm,
                                         const float* __restrict__ bsm,
                                         const u64* __restrict__ in,
                                         u64* __restrict__ acc)
{
    constexpr int QO = NOUT / 4;   // ulonglong2 per weight row
#pragma unroll
    for (int q = 0; q < QO; q++) {
        ulonglong2 b = ((const ulonglong2*)bsm)[q];
        acc[2 * q] = b.x; acc[2 * q + 1] = b.y;
    }
#pragma unroll
    for (int ip = 0; ip < NIN / 2; ip++) {
        float2 f2 = upk2(in[ip]);
        u64 f0 = pk2(f2.x, f2.x);
        u64 f1 = pk2(f2.y, f2.y);
        const ulonglong2* w0 = (const ulonglong2*)(wsm + (2 * ip) * NOUT);
        const ulonglong2* w1 = (const ulonglong2*)(wsm + (2 * ip + 1) * NOUT);
#pragma unroll
        for (int q = 0; q < QO; q++) {
            ulonglong2 a = w0[q];
            acc[2 * q]     = ffma2(f0, a.x, acc[2 * q]);
            acc[2 * q + 1] = ffma2(f0, a.y, acc[2 * q + 1]);
        }
#pragma unroll
        for (int q = 0; q < QO; q++) {
            ulonglong2 b = w1[q];
            acc[2 * q]     = ffma2(f1, b.x, acc[2 * q]);
            acc[2 * q + 1] = ffma2(f1, b.y, acc[2 * q + 1]);
        }
    }
}

template<int N2>
__device__ __forceinline__ void relu_pk(u64* v) {
#pragma unroll
    for (int q = 0; q < N2; q++) {
        float2 t = upk2(v[q]);
        v[q] = pk2(fmaxf(t.x, 0.f), fmaxf(t.y, 0.f));
    }
}

__global__ void __launch_bounds__(128, 3)
nerf_fused_kernel(const float* __restrict__ coords,
                  const float* __restrict__ dirs,
                  const u64*   __restrict__ emb,   // float2 pairs as u64
                  const float* __restrict__ dw1, const float* __restrict__ db1,
                  const float* __restrict__ dw2, const float* __restrict__ db2,
                  const float* __restrict__ cw1, const float* __restrict__ cb1,
                  const float* __restrict__ cw2, const float* __restrict__ cb2,
                  const float* __restrict__ cw3, const float* __restrict__ cb3,
                  const float* __restrict__ cw4, const float* __restrict__ cb4,
                  float* __restrict__ out)
{
    extern __shared__ float sm[];

    // ---- cooperative weight load into shared ----
    {
        const float* srcs[12] = {dw1, db1, dw2, db2, cw1, cb1, cw2, cb2, cw3, cb3, cw4, cb4};
        const int    offs[12] = {O_DW1, O_DB1, O_DW2, O_DB2, O_CW1, O_CB1,
                                 O_CW2, O_CB2, O_CW3, O_CB3, O_CW4, O_CB4};
        const int    cnts[12] = {2048, 64, 1024, 16, 2048, 64, 4096, 64, 4096, 64, 192, 3};
        for (int a = 0; a < 12; a++) {
            const float* s = srcs[a];
            int o = offs[a], c = cnts[a];
            for (int i = threadIdx.x; i < c; i += 128)
                sm[o + i] = s[i];
        }
    }
    __syncthreads();

    const int p = blockIdx.x * 128 + threadIdx.x;

    const float cx = coords[3 * p + 0];
    const float cy = coords[3 * p + 1];
    const float cz = coords[3 * p + 2];
    // load dirs early to hide latency under the hash/MLP work
    float dxr = dirs[3 * p + 0];
    float dyr = dirs[3 * p + 1];
    float dzr = dirs[3 * p + 2];

    // ---------------- hash-grid encoding (packed feature pairs) ----------------
    u64 fpk[16];
    const float RESV[16] = {16.f, 20.f, 25.f, 32.f, 40.f, 50.f, 64.f, 80.f,
                            101.f, 128.f, 161.f, 203.f, 256.f, 322.f, 406.f, 512.f};

#pragma unroll
    for (int l = 0; l < NLEV; l++) {
        const float r = RESV[l];
        float fx = cx * r, fy = cy * r, fz = cz * r;
        float xf = floorf(fx), yf = floorf(fy), zf = floorf(fz);
        float tx = fx - xf, ty = fy - yf, tz = fz - zf;
        uint32_t px = (uint32_t)xf, py = (uint32_t)yf, pz = (uint32_t)zf;

        uint32_t hx0 = px;                  uint32_t hx1 = px + 1u;
        uint32_t hy0 = py * 2654435761u;    uint32_t hy1 = hy0 + 2654435761u;
        uint32_t hz0 = pz * 805459861u;     uint32_t hz1 = hz0 + 805459861u;

        const u64* t = emb + ((size_t)l << 19);
        u64 e000 = __ldg(t + ((hx0 ^ hy0 ^ hz0) & TMASK));
        u64 e001 = __ldg(t + ((hx0 ^ hy0 ^ hz1) & TMASK));
        u64 e010 = __ldg(t + ((hx0 ^ hy1 ^ hz0) & TMASK));
        u64 e011 = __ldg(t + ((hx0 ^ hy1 ^ hz1) & TMASK));
        u64 e100 = __ldg(t + ((hx1 ^ hy0 ^ hz0) & TMASK));
        u64 e101 = __ldg(t + ((hx1 ^ hy0 ^ hz1) & TMASK));
        u64 e110 = __ldg(t + ((hx1 ^ hy1 ^ hz0) & TMASK));
        u64 e111 = __ldg(t + ((hx1 ^ hy1 ^ hz1) & TMASK));

        float ux = 1.f - tx, uy = 1.f - ty, uz = 1.f - tz;
        float wxy00 = ux * uy, wxy01 = ux * ty, wxy10 = tx * uy, wxy11 = tx * ty;

        u64 a = 0ULL;  // {0.f, 0.f}
        float w;
        w = wxy00 * uz; a = ffma2(pk2(w, w), e000, a);
        w = wxy00 * tz; a = ffma2(pk2(w, w), e001, a);
        w = wxy01 * uz; a = ffma2(pk2(w, w), e010, a);
        w = wxy01 * tz; a = ffma2(pk2(w, w), e011, a);
        w = wxy10 * uz; a = ffma2(pk2(w, w), e100, a);
        w = wxy10 * tz; a = ffma2(pk2(w, w), e101, a);
        w = wxy11 * uz; a = ffma2(pk2(w, w), e110, a);
        w = wxy11 * tz; a = ffma2(pk2(w, w), e111, a);
        fpk[l] = a;
    }

    // ---------------- density MLP: 32 -> 64 (relu) -> 16 ----------------
    u64 h[32];
    layer_pk<32, 64>(&sm[O_DW1], &sm[O_DB1], fpk, h);
    relu_pk<32>(h);

    u64 dacc[8];
    layer_pk<64, 16>(&sm[O_DW2], &sm[O_DB2], h, dacc);

    float2 d0 = upk2(dacc[0]);
    const float density = expf(d0.x);

    // ---------------- SH deg-4 encoding ----------------
    float nrm = sqrtf(dxr * dxr + dyr * dyr + dzr * dzr);
    float x = dxr / nrm, y = dyr / nrm, z = dzr / nrm;
    // reference applies (d+1)/2*2-1 — identity up to rounding
    x = ((x + 1.f) * 0.5f) * 2.f - 1.f;
    y = ((y + 1.f) * 0.5f) * 2.f - 1.f;
    z = ((z + 1.f) * 0.5f) * 2.f - 1.f;

    float xx = x * x, yy = y * y, zz = z * z;
    float xy = x * y, yz = y * z, xz = x * z;

    u64 ipk[16];
    ipk[0] = pk2(0.28209479177387814f,           -0.48860251190291987f * y);
    ipk[1] = pk2(0.48860251190291987f * z,       -0.48860251190291987f * x);
    ipk[2] = pk2(1.0925484305920792f * xy,       -1.0925484305920792f * yz);
    ipk[3] = pk2(0.94617469575756f * zz - 0.31539156525252f,
                 -1.0925484305920792f * xz);
    ipk[4] = pk2(0.5462742152960396f * (xx - yy),
                 0.5900435899266435f * y * (-3.0f * xx + yy));
    ipk[5] = pk2(2.890611442640554f * xy * z,
                 0.4570457994644657f * y * (1.0f - 5.0f * zz));
    ipk[6] = pk2(0.3731763325901154f * z * (5.0f * zz - 3.0f),
                 0.4570457994644657f * x * (1.0f - 5.0f * zz));
    ipk[7] = pk2(1.445305721320277f * z * (xx - yy),
                 0.5900435899266435f * x * (xx - 3.0f * yy));
#pragma unroll
    for (int k = 0; k < 8; k++) ipk[8 + k] = dacc[k];

    // ---------------- color MLP ----------------
    u64 xa[32], xb[32];
    layer_pk<32, 64>(&sm[O_CW1], &sm[O_CB1], ipk, xa);
    relu_pk<32>(xa);
    layer_pk<64, 64>(&sm[O_CW2], &sm[O_CB2], xa, xb);
    relu_pk<32>(xb);
    layer_pk<64, 64>(&sm[O_CW3], &sm[O_CB3], xb, xa);
    relu_pk<32>(xa);

    // layer 4: 64 -> 3 (sigmoid), scalar
    float c0 = sm[O_CB4 + 0], c1 = sm[O_CB4 + 1], c2 = sm[O_CB4 + 2];
#pragma unroll
    for (int q = 0; q < 32; q++) {
        float2 v = upk2(xa[q]);
        const float* w0 = &sm[O_CW4 + (2 * q) * 3];
        c0 = fmaf(v.x, w0[0], c0);
        c1 = fmaf(v.x, w0[1], c1);
        c2 = fmaf(v.x, w0[2], c2);
        c0 = fmaf(v.y, w0[3], c0);
        c1 = fmaf(v.y, w0[4], c1);
        c2 = fmaf(v.y, w0[5], c2);
    }
    c0 = 1.f / (1.f + expf(-c0));
    c1 = 1.f / (1.f + expf(-c1));
    c2 = 1.f / (1.f + expf(-c2));

    // ---------------- outputs: [density(B)] then [color(B,3)] ----------------
    out[p] = density;
    out[NPTS + 3 * p + 0] = c0;
    out[NPTS + 3 * p + 1] = c1;
    out[NPTS + 3 * p + 2] = c2;
}

extern "C" void kernel_launch(void* const* d_in, const int* in_sizes, int n_in,
                              void* d_out, int out_size)
{
    const float* coords = (const float*)d_in[0];
    const float* dirs   = (const float*)d_in[1];
    const u64*   emb    = (const u64*)d_in[2];
    const float* dw1 = (const float*)d_in[3];
    const float* db1 = (const float*)d_in[4];
    const float* dw2 = (const float*)d_in[5];
    const float* db2 = (const float*)d_in[6];
    const float* cw1 = (const float*)d_in[7];
    const float* cb1 = (const float*)d_in[8];
    const float* cw2 = (const float*)d_in[9];
    const float* cb2 = (const float*)d_in[10];
    const float* cw3 = (const float*)d_in[11];
    const float* cb3 = (const float*)d_in[12];
    const float* cw4 = (const float*)d_in[13];
    const float* cb4 = (const float*)d_in[14];
    float* out = (float*)d_out;

    cudaFuncSetAttribute(nerf_fused_kernel,
                         cudaFuncAttributeMaxDynamicSharedMemorySize, SMEM_BYTES);

    nerf_fused_kernel<<<NPTS / 128, 128, SMEM_BYTES>>>(
        coords, dirs, emb,
        dw1, db1, dw2, db2,
        cw1, cb1, cw2, cb2, cw3, cb3, cw4, cb4,
        out);
}

// round 7
// speedup vs baseline: 1.4459x; 1.1661x over previous
#include <cuda_runtime.h>
#include <stdint.h>

#define NPTS   262144
#define NTILES 2048
#define TMASK  0x7FFFFu
#define RS     68            // staging row stride (floats): banks 4g+tig bijective

// smem float offsets
#define W_L1 0               // 32x64 frag-ordered  (2048)
#define W_L2 2048            // 64x16               (1024)
#define W_C1 3072            // 32x64               (2048)
#define W_C2 5120            // 64x64               (4096)
#define W_C3 9216            // 64x64               (4096)
#define W_C4 13312           // 64x8 (3 real cols)  (512)
#define BIAS 13824           // db1(64) db2(16) cb1(64) cb2(64) cb3(64) cb4(8)
#define STG  14112           // 4 warps x 32 x RS
#define SMEM_FLOATS (STG + 4 * 32 * RS)
#define SMEM_BYTES  (SMEM_FLOATS * 4)
#define NCTA 304

typedef unsigned long long u64;

__device__ __forceinline__ uint32_t cvt_tf32(float x) {
    uint32_t r; asm("cvt.rna.tf32.f32 %0, %1;" : "=r"(r) : "f"(x)); return r;
}

__device__ __forceinline__ void mma8(float* d, const uint32_t* a, uint32_t b0, uint32_t b1) {
    asm volatile(
        "mma.sync.aligned.m16n8k8.row.col.f32.tf32.tf32.f32 "
        "{%0,%1,%2,%3},{%4,%5,%6,%7},{%8,%9},{%0,%1,%2,%3};"
        : "+f"(d[0]), "+f"(d[1]), "+f"(d[2]), "+f"(d[3])
        : "r"(a[0]), "r"(a[1]), "r"(a[2]), "r"(a[3]), "r"(b0), "r"(b1));
}

// Compute one 16-row m-tile: acc[Nt][4] = A(16xK from staging) @ W(KxN), 3-pass 2xTF32.
template<int K, int N>
__device__ __forceinline__ void mma_compute(const float* __restrict__ Wf,
                                            const float* __restrict__ Aw,
                                            int m, int lane, float acc[N / 8][4])
{
    constexpr int Kt = K / 8, Nt = N / 8;
    const int g = lane >> 2, tig = lane & 3;
    uint32_t ah[Kt][4], al[Kt][4];
    const float* a0p = Aw + (16 * m + g) * RS + tig;
    const float* a1p = a0p + 8 * RS;
#pragma unroll
    for (int kt = 0; kt < Kt; kt++) {
        float v0 = a0p[kt * 8],     v1 = a1p[kt * 8];
        float v2 = a0p[kt * 8 + 4], v3 = a1p[kt * 8 + 4];
        ah[kt][0] = cvt_tf32(v0); al[kt][0] = cvt_tf32(v0 - __uint_as_float(ah[kt][0]));
        ah[kt][1] = cvt_tf32(v1); al[kt][1] = cvt_tf32(v1 - __uint_as_float(ah[kt][1]));
        ah[kt][2] = cvt_tf32(v2); al[kt][2] = cvt_tf32(v2 - __uint_as_float(ah[kt][2]));
        ah[kt][3] = cvt_tf32(v3); al[kt][3] = cvt_tf32(v3 - __uint_as_float(ah[kt][3]));
    }
#pragma unroll
    for (int nt = 0; nt < Nt; nt++) {
        acc[nt][0] = acc[nt][1] = acc[nt][2] = acc[nt][3] = 0.f;
#pragma unroll
        for (int kt = 0; kt < Kt; kt++) {
            float2 b = *(const float2*)(Wf + (nt * Kt + kt) * 64 + lane * 2);
            uint32_t bh0 = cvt_tf32(b.x), bh1 = cvt_tf32(b.y);
            uint32_t bl0 = cvt_tf32(b.x - __uint_as_float(bh0));
            uint32_t bl1 = cvt_tf32(b.y - __uint_as_float(bh1));
            mma8(acc[nt], ah[kt], bh0, bh1);
            mma8(acc[nt], al[kt], bh0, bh1);
            mma8(acc[nt], ah[kt], bl0, bl1);
        }
    }
}

// relu layer: reads staging cols 0..K-1, writes relu(acc+bias) to cols 0..N-1
template<int K, int N>
__device__ __forceinline__ void layer_relu(const float* __restrict__ Wf,
                                           const float* __restrict__ bias,
                                           float* __restrict__ Aw, int lane)
{
    constexpr int Nt = N / 8;
    const int g = lane >> 2, tig = lane & 3;
#pragma unroll
    for (int m = 0; m < 2; m++) {
        float acc[Nt][4];
        mma_compute<K, N>(Wf, Aw, m, lane, acc);
        __syncwarp();
        float* s0 = Aw + (16 * m + g) * RS + 2 * tig;
#pragma unroll
        for (int nt = 0; nt < Nt; nt++) {
            float b0 = bias[nt * 8 + 2 * tig], b1 = bias[nt * 8 + 2 * tig + 1];
            *(float2*)(s0 + nt * 8) =
                make_float2(fmaxf(acc[nt][0] + b0, 0.f), fmaxf(acc[nt][1] + b1, 0.f));
            *(float2*)(s0 + 8 * RS + nt * 8) =
                make_float2(fmaxf(acc[nt][2] + b0, 0.f), fmaxf(acc[nt][3] + b1, 0.f));
        }
        __syncwarp();
    }
}

// density layer 2: K=64 -> N=16, NO relu, writes to staging cols 16..31
__device__ __forceinline__ void layer_l2(const float* __restrict__ Wf,
                                         const float* __restrict__ bias,
                                         float* __restrict__ Aw, int lane)
{
    const int g = lane >> 2, tig = lane & 3;
#pragma unroll
    for (int m = 0; m < 2; m++) {
        float acc[2][4];
        mma_compute<64, 16>(Wf, Aw, m, lane, acc);
        __syncwarp();
        float* s0 = Aw + (16 * m + g) * RS + 16 + 2 * tig;
#pragma unroll
        for (int nt = 0; nt < 2; nt++) {
            float b0 = bias[nt * 8 + 2 * tig], b1 = bias[nt * 8 + 2 * tig + 1];
            *(float2*)(s0 + nt * 8) =
                make_float2(acc[nt][0] + b0, acc[nt][1] + b1);
            *(float2*)(s0 + 8 * RS + nt * 8) =
                make_float2(acc[nt][2] + b0, acc[nt][3] + b1);
        }
        __syncwarp();
    }
}

__device__ __forceinline__ float sigm(float v) { return 1.f / (1.f + expf(-v)); }

// color layer 4: K=64 -> N=8 (3 real), sigmoid, store to global
__device__ __forceinline__ void layer_c4(const float* __restrict__ Wf,
                                         const float* __restrict__ bias,
                                         const float* __restrict__ Aw, int lane,
                                         float* __restrict__ out, int pbase)
{
    const int g = lane >> 2, tig = lane & 3;
#pragma unroll
    for (int m = 0; m < 2; m++) {
        float acc[1][4];
        mma_compute<64, 8>(Wf, Aw, m, lane, acc);
        int r0 = pbase + 16 * m + g;
        int c = 2 * tig;
        if (c < 3) {
            float b = bias[c];
            out[NPTS + 3 * r0 + c]       = sigm(acc[0][0] + b);
            out[NPTS + 3 * (r0 + 8) + c] = sigm(acc[0][2] + b);
        }
        if (c + 1 < 3) {
            float b = bias[c + 1];
            out[NPTS + 3 * r0 + c + 1]       = sigm(acc[0][1] + b);
            out[NPTS + 3 * (r0 + 8) + c + 1] = sigm(acc[0][3] + b);
        }
    }
    __syncwarp();   // protect staging reads from next tile's feature stores
}

// stage one weight matrix into B-fragment order:
// Wf[((nt*Kt+kt)*32 + lane)*2 + j] = W[kt*8 + lane%4 + 4j][nt*8 + lane/4]
__device__ __forceinline__ void stage_w(float* __restrict__ sm, const float* __restrict__ w,
                                        int Kt, int Nt, int rN, int off, int tid)
{
    int tot = Kt * Nt * 64;
    for (int idx = tid; idx < tot; idx += 128) {
        int lane = (idx >> 1) & 31, j = idx & 1, ktnt = idx >> 6;
        int kt = ktnt % Kt, nt = ktnt / Kt;
        int k = kt * 8 + (lane & 3) + 4 * j;
        int n = nt * 8 + (lane >> 2);
        sm[off + idx] = (n < rN) ? w[k * rN + n] : 0.f;
    }
}

__global__ void __launch_bounds__(128)
nerf_mma_kernel(const float* __restrict__ coords,
                const float* __restrict__ dirs,
                const u64*   __restrict__ emb,
                const float* __restrict__ dw1, const float* __restrict__ db1,
                const float* __restrict__ dw2, const float* __restrict__ db2,
                const float* __restrict__ cw1, const float* __restrict__ cb1,
                const float* __restrict__ cw2, const float* __restrict__ cb2,
                const float* __restrict__ cw3, const float* __restrict__ cb3,
                const float* __restrict__ cw4, const float* __restrict__ cb4,
                float* __restrict__ out)
{
    extern __shared__ float sm[];
    const int tid = threadIdx.x;

    // ---- stage weights (frag-ordered) + biases ----
    stage_w(sm, dw1, 4, 8, 64, W_L1, tid);
    stage_w(sm, dw2, 8, 2, 16, W_L2, tid);
    stage_w(sm, cw1, 4, 8, 64, W_C1, tid);
    stage_w(sm, cw2, 8, 8, 64, W_C2, tid);
    stage_w(sm, cw3, 8, 8, 64, W_C3, tid);
    stage_w(sm, cw4, 8, 1,  3, W_C4, tid);
    for (int i = tid; i < 64; i += 128) sm[BIAS + i] = db1[i];
    for (int i = tid; i < 16; i += 128) sm[BIAS + 64 + i] = db2[i];
    for (int i = tid; i < 64; i += 128) sm[BIAS + 80 + i] = cb1[i];
    for (int i = tid; i < 64; i += 128) sm[BIAS + 144 + i] = cb2[i];
    for (int i = tid; i < 64; i += 128) sm[BIAS + 208 + i] = cb3[i];
    for (int i = tid; i < 8; i += 128)  sm[BIAS + 272 + i] = (i < 3) ? cb4[i] : 0.f;
    __syncthreads();

    const int lane = tid & 31, warp = tid >> 5;
    float* Aw = sm + STG + warp * (32 * RS);

    const float RESV[16] = {16.f, 20.f, 25.f, 32.f, 40.f, 50.f, 64.f, 80.f,
                            101.f, 128.f, 161.f, 203.f, 256.f, 322.f, 406.f, 512.f};

    for (int t = blockIdx.x; t < NTILES; t += gridDim.x) {
        const int p = t * 128 + warp * 32 + lane;

        // ---------- hash-grid encode (1 point per lane) ----------
        const float cx = coords[3 * p + 0];
        const float cy = coords[3 * p + 1];
        const float cz = coords[3 * p + 2];
        float dxr = dirs[3 * p + 0];
        float dyr = dirs[3 * p + 1];
        float dzr = dirs[3 * p + 2];

        float feat[32];
#pragma unroll
        for (int l = 0; l < 16; l++) {
            const float r = RESV[l];
            float fx = cx * r, fy = cy * r, fz = cz * r;
            float xf = floorf(fx), yf = floorf(fy), zf = floorf(fz);
            float tx = fx - xf, ty = fy - yf, tz = fz - zf;
            uint32_t px = (uint32_t)xf, py = (uint32_t)yf, pz = (uint32_t)zf;
            uint32_t hx0 = px,                hx1 = px + 1u;
            uint32_t hy0 = py * 2654435761u,  hy1 = hy0 + 2654435761u;
            uint32_t hz0 = pz * 805459861u,   hz1 = hz0 + 805459861u;
            const u64* tt = emb + ((size_t)l << 19);
            u64 e000 = __ldg(tt + ((hx0 ^ hy0 ^ hz0) & TMASK));
            u64 e001 = __ldg(tt + ((hx0 ^ hy0 ^ hz1) & TMASK));
            u64 e010 = __ldg(tt + ((hx0 ^ hy1 ^ hz0) & TMASK));
            u64 e011 = __ldg(tt + ((hx0 ^ hy1 ^ hz1) & TMASK));
            u64 e100 = __ldg(tt + ((hx1 ^ hy0 ^ hz0) & TMASK));
            u64 e101 = __ldg(tt + ((hx1 ^ hy0 ^ hz1) & TMASK));
            u64 e110 = __ldg(tt + ((hx1 ^ hy1 ^ hz0) & TMASK));
            u64 e111 = __ldg(tt + ((hx1 ^ hy1 ^ hz1) & TMASK));

            float ux = 1.f - tx, uy = 1.f - ty, uz = 1.f - tz;
            float w00 = ux * uy, w01 = ux * ty, w10 = tx * uy, w11 = tx * ty;
            float2 v; float a0 = 0.f, a1 = 0.f, w;
            w = w00 * uz; v = *(float2*)&e000; a0 = fmaf(w, v.x, a0); a1 = fmaf(w, v.y, a1);
            w = w00 * tz; v = *(float2*)&e001; a0 = fmaf(w, v.x, a0); a1 = fmaf(w, v.y, a1);
            w = w01 * uz; v = *(float2*)&e010; a0 = fmaf(w, v.x, a0); a1 = fmaf(w, v.y, a1);
            w = w01 * tz; v = *(float2*)&e011; a0 = fmaf(w, v.x, a0); a1 = fmaf(w, v.y, a1);
            w = w10 * uz; v = *(float2*)&e100; a0 = fmaf(w, v.x, a0); a1 = fmaf(w, v.y, a1);
            w = w10 * tz; v = *(float2*)&e101; a0 = fmaf(w, v.x, a0); a1 = fmaf(w, v.y, a1);
            w = w11 * uz; v = *(float2*)&e110; a0 = fmaf(w, v.x, a0); a1 = fmaf(w, v.y, a1);
            w = w11 * tz; v = *(float2*)&e111; a0 = fmaf(w, v.x, a0); a1 = fmaf(w, v.y, a1);
            feat[2 * l] = a0; feat[2 * l + 1] = a1;
        }

        // stage features (row = lane, cols 0..31)
        float* frow = Aw + lane * RS;
#pragma unroll
        for (int i = 0; i < 8; i++)
            *(float4*)(frow + 4 * i) =
                make_float4(feat[4 * i], feat[4 * i + 1], feat[4 * i + 2], feat[4 * i + 3]);
        __syncwarp();

        // ---------- density MLP ----------
        layer_relu<32, 64>(sm + W_L1, sm + BIAS, Aw, lane);
        layer_l2(sm + W_L2, sm + BIAS + 64, Aw, lane);

        // density output (col 16 = density_out[0] of own row)
        out[p] = expf(frow[16]);

        // ---------- SH deg-4 into cols 0..15 ----------
        {
            float nrm = sqrtf(dxr * dxr + dyr * dyr + dzr * dzr);
            float x = dxr / nrm, y = dyr / nrm, z = dzr / nrm;
            x = ((x + 1.f) * 0.5f) * 2.f - 1.f;
            y = ((y + 1.f) * 0.5f) * 2.f - 1.f;
            z = ((z + 1.f) * 0.5f) * 2.f - 1.f;
            float xx = x * x, yy = y * y, zz = z * z;
            float xy = x * y, yz = y * z, xz = x * z;
            *(float4*)(frow + 0) = make_float4(
                0.28209479177387814f,
                -0.48860251190291987f * y,
                 0.48860251190291987f * z,
                -0.48860251190291987f * x);
            *(float4*)(frow + 4) = make_float4(
                 1.0925484305920792f * xy,
                -1.0925484305920792f * yz,
                 0.94617469575756f * zz - 0.31539156525252f,
                -1.0925484305920792f * xz);
            *(float4*)(frow + 8) = make_float4(
                 0.5462742152960396f * (xx - yy),
                 0.5900435899266435f * y * (-3.0f * xx + yy),
                 2.890611442640554f * xy * z,
                 0.4570457994644657f * y * (1.0f - 5.0f * zz));
            *(float4*)(frow + 12) = make_float4(
                 0.3731763325901154f * z * (5.0f * zz - 3.0f),
                 0.4570457994644657f * x * (1.0f - 5.0f * zz),
                 1.445305721320277f * z * (xx - yy),
                 0.5900435899266435f * x * (xx - 3.0f * yy));
        }
        __syncwarp();

        // ---------- color MLP ----------
        layer_relu<32, 64>(sm + W_C1, sm + BIAS + 80,  Aw, lane);
        layer_relu<64, 64>(sm + W_C2, sm + BIAS + 144, Aw, lane);
        layer_relu<64, 64>(sm + W_C3, sm + BIAS + 208, Aw, lane);
        layer_c4(sm + W_C4, sm + BIAS + 272, Aw, lane, out, t * 128 + warp * 32);
    }
}

extern "C" void kernel_launch(void* const* d_in, const int* in_sizes, int n_in,
                              void* d_out, int out_size)
{
    const float* coords = (const float*)d_in[0];
    const float* dirs   = (const float*)d_in[1];
    const u64*   emb    = (const u64*)d_in[2];
    const float* dw1 = (const float*)d_in[3];
    const float* db1 = (const float*)d_in[4];
    const float* dw2 = (const float*)d_in[5];
    const float* db2 = (const float*)d_in[6];
    const float* cw1 = (const float*)d_in[7];
    const float* cb1 = (const float*)d_in[8];
    const float* cw2 = (const float*)d_in[9];
    const float* cb2 = (const float*)d_in[10];
    const float* cw3 = (const float*)d_in[11];
    const float* cb3 = (const float*)d_in[12];
    const float* cw4 = (const float*)d_in[13];
    const float* cb4 = (const float*)d_in[14];
    float* out = (float*)d_out;

    cudaFuncSetAttribute(nerf_mma_kernel,
                         cudaFuncAttributeMaxDynamicSharedMemorySize, SMEM_BYTES);

    nerf_mma_kernel<<<NCTA, 128, SMEM_BYTES>>>(
        coords, dirs, emb,
        dw1, db1, dw2, db2,
        cw1, cb1, cw2, cb2, cw3, cb3, cw4, cb4,
        out);
}

// round 8
// speedup vs baseline: 2.2308x; 1.5429x over previous
#include <cuda_runtime.h>
#include <stdint.h>

#define NPTS    262144
#define NWTILES 8192          // 8192 warp-tiles of 32 points
#define TMASK   0x7FFFFu
#define RS      72            // staging row stride (floats); banks 8g+2tig conflict-free
#define THREADS 384
#define NWARP   12
#define NCTA    148

// weight fragment arrays (uint4 units)
#define WF_L1 0               // Kt2 Nt8 -> 512
#define WF_L2 512             // Kt4 Nt2 -> 256
#define WF_C1 768             // Kt2 Nt8 -> 512
#define WF_C2 1280            // Kt4 Nt8 -> 1024
#define WF_C3 2304            // Kt4 Nt8 -> 1024
#define WF_C4 3328            // Kt4 Nt1 -> 128
#define WF_TOT 3456
#define BIAS_F (WF_TOT * 4)   // float index 13824; db1(64) db2(16) cb1(64) cb2(64) cb3(64) cb4(8)
#define STG_F  (BIAS_F + 280) // 14104 (byte 56416, 16B aligned)
#define SMEM_FLOATS (STG_F + NWARP * 32 * RS)
#define SMEM_BYTES  (SMEM_FLOATS * 4)

typedef unsigned long long u64;

// pack two fp32 -> bf16x2 (low half = first arg)
__device__ __forceinline__ uint32_t pkb(float lo, float hi) {
    uint32_t r; asm("cvt.rn.bf16x2.f32 %0, %1, %2;" : "=r"(r) : "f"(hi), "f"(lo)); return r;
}
__device__ __forceinline__ float lof(uint32_t u) { return __uint_as_float(u << 16); }
__device__ __forceinline__ float hif(uint32_t u) { return __uint_as_float(u & 0xffff0000u); }

__device__ __forceinline__ void mma16(float* d, const uint32_t* a, uint32_t b0, uint32_t b1) {
    asm volatile(
        "mma.sync.aligned.m16n8k16.row.col.f32.bf16.bf16.f32 "
        "{%0,%1,%2,%3},{%4,%5,%6,%7},{%8,%9},{%0,%1,%2,%3};"
        : "+f"(d[0]), "+f"(d[1]), "+f"(d[2]), "+f"(d[3])
        : "r"(a[0]), "r"(a[1]), "r"(a[2]), "r"(a[3]), "r"(b0), "r"(b1));
}

// acc[Nt][4] = A(16xK fp32 staging) @ W(KxN), 3-pass bf16 (AhBh + AlBh + AhBl)
template<int K, int N>
__device__ __forceinline__ void mma_compute(const uint4* __restrict__ Wf,
                                            const float* __restrict__ Aw,
                                            int m, int lane, float acc[N / 8][4])
{
    constexpr int Kt = K / 16, Nt = N / 8;
    const int g = lane >> 2, tig = lane & 3;
#pragma unroll
    for (int nt = 0; nt < Nt; nt++)
        acc[nt][0] = acc[nt][1] = acc[nt][2] = acc[nt][3] = 0.f;
    const float* base = Aw + (16 * m + g) * RS + 2 * tig;
#pragma unroll
    for (int kt = 0; kt < Kt; kt++) {
        const float* ar = base + kt * 16;
        float2 va = *(const float2*)(ar);               // row g,   k0..k0+1
        float2 vc = *(const float2*)(ar + 8 * RS);      // row g+8, k0..k0+1
        float2 vb = *(const float2*)(ar + 8);           // row g,   k0+8..k0+9
        float2 vd = *(const float2*)(ar + 8 * RS + 8);  // row g+8, k0+8..k0+9
        uint32_t ah[4], al[4];
        ah[0] = pkb(va.x, va.y); al[0] = pkb(va.x - lof(ah[0]), va.y - hif(ah[0]));
        ah[1] = pkb(vc.x, vc.y); al[1] = pkb(vc.x - lof(ah[1]), vc.y - hif(ah[1]));
        ah[2] = pkb(vb.x, vb.y); al[2] = pkb(vb.x - lof(ah[2]), vb.y - hif(ah[2]));
        ah[3] = pkb(vd.x, vd.y); al[3] = pkb(vd.x - lof(ah[3]), vd.y - hif(ah[3]));
#pragma unroll
        for (int nt = 0; nt < Nt; nt++) {
            uint4 B = Wf[(nt * Kt + kt) * 32 + lane];
            mma16(acc[nt], ah, B.x, B.y);
            mma16(acc[nt], al, B.x, B.y);
            mma16(acc[nt], ah, B.z, B.w);
        }
    }
}

// relu layer: reads cols 0..K-1, writes relu(acc+bias) to cols 0..N-1
template<int K, int N>
__device__ __forceinline__ void layer_relu(const uint4* __restrict__ Wf,
                                           const float* __restrict__ bias,
                                           float* __restrict__ Aw, int lane)
{
    constexpr int Nt = N / 8;
    const int g = lane >> 2, tig = lane & 3;
#pragma unroll
    for (int m = 0; m < 2; m++) {
        float acc[Nt][4];
        mma_compute<K, N>(Wf, Aw, m, lane, acc);
        __syncwarp();
        float* s0 = Aw + (16 * m + g) * RS + 2 * tig;
#pragma unroll
        for (int nt = 0; nt < Nt; nt++) {
            float b0 = bias[nt * 8 + 2 * tig], b1 = bias[nt * 8 + 2 * tig + 1];
            *(float2*)(s0 + nt * 8) =
                make_float2(fmaxf(acc[nt][0] + b0, 0.f), fmaxf(acc[nt][1] + b1, 0.f));
            *(float2*)(s0 + 8 * RS + nt * 8) =
                make_float2(fmaxf(acc[nt][2] + b0, 0.f), fmaxf(acc[nt][3] + b1, 0.f));
        }
        __syncwarp();
    }
}

// density layer 2: 64 -> 16, no relu, writes to cols 16..31
__device__ __forceinline__ void layer_l2(const uint4* __restrict__ Wf,
                                         const float* __restrict__ bias,
                                         float* __restrict__ Aw, int lane)
{
    const int g = lane >> 2, tig = lane & 3;
#pragma unroll
    for (int m = 0; m < 2; m++) {
        float acc[2][4];
        mma_compute<64, 16>(Wf, Aw, m, lane, acc);
        __syncwarp();
        float* s0 = Aw + (16 * m + g) * RS + 16 + 2 * tig;
#pragma unroll
        for (int nt = 0; nt < 2; nt++) {
            float b0 = bias[nt * 8 + 2 * tig], b1 = bias[nt * 8 + 2 * tig + 1];
            *(float2*)(s0 + nt * 8) = make_float2(acc[nt][0] + b0, acc[nt][1] + b1);
            *(float2*)(s0 + 8 * RS + nt * 8) = make_float2(acc[nt][2] + b0, acc[nt][3] + b1);
        }
        __syncwarp();
    }
}

__device__ __forceinline__ float sigm(float v) { return 1.f / (1.f + expf(-v)); }

// color layer 4: 64 -> 8 (3 real), sigmoid, store to global
__device__ __forceinline__ void layer_c4(const uint4* __restrict__ Wf,
                                         const float* __restrict__ bias,
                                         const float* __restrict__ Aw, int lane,
                                         float* __restrict__ out, int pbase)
{
    const int g = lane >> 2, tig = lane & 3;
#pragma unroll
    for (int m = 0; m < 2; m++) {
        float acc[1][4];
        mma_compute<64, 8>(Wf, Aw, m, lane, acc);
        int r0 = pbase + 16 * m + g;
        int c = 2 * tig;
        if (c < 3) {
            float b = bias[c];
            out[NPTS + 3 * r0 + c]       = sigm(acc[0][0] + b);
            out[NPTS + 3 * (r0 + 8) + c] = sigm(acc[0][2] + b);
        }
        if (c + 1 < 3) {
            float b = bias[c + 1];
            out[NPTS + 3 * r0 + c + 1]       = sigm(acc[0][1] + b);
            out[NPTS + 3 * (r0 + 8) + c + 1] = sigm(acc[0][3] + b);
        }
    }
    __syncwarp();
}

// stage one weight matrix into bf16 hi/lo packed B-fragment order
__device__ __forceinline__ void stage_w(uint4* __restrict__ dst, const float* __restrict__ w,
                                        int Kt, int Nt, int rN, int tid)
{
    int tot = Kt * Nt * 32;
    for (int idx = tid; idx < tot; idx += THREADS) {
        int lane = idx & 31, f = idx >> 5;
        int kt = f % Kt, nt = f / Kt;
        int g = lane >> 2, tig = lane & 3;
        int n = nt * 8 + g;
        int k0 = kt * 16 + 2 * tig;
        float w00 = 0.f, w01 = 0.f, w10 = 0.f, w11 = 0.f;
        if (n < rN) {
            w00 = w[k0 * rN + n];       w01 = w[(k0 + 1) * rN + n];
            w10 = w[(k0 + 8) * rN + n]; w11 = w[(k0 + 9) * rN + n];
        }
        uint32_t h0 = pkb(w00, w01), h1 = pkb(w10, w11);
        uint32_t l0 = pkb(w00 - lof(h0), w01 - hif(h0));
        uint32_t l1 = pkb(w10 - lof(h1), w11 - hif(h1));
        dst[idx] = make_uint4(h0, h1, l0, l1);
    }
}

__global__ void __launch_bounds__(THREADS, 1)
nerf_mma_kernel(const float* __restrict__ coords,
                const float* __restrict__ dirs,
                const u64*   __restrict__ emb,
                const float* __restrict__ dw1, const float* __restrict__ db1,
                const float* __restrict__ dw2, const float* __restrict__ db2,
                const float* __restrict__ cw1, const float* __restrict__ cb1,
                const float* __restrict__ cw2, const float* __restrict__ cb2,
                const float* __restrict__ cw3, const float* __restrict__ cb3,
                const float* __restrict__ cw4, const float* __restrict__ cb4,
                float* __restrict__ out)
{
    extern __shared__ float sm[];
    uint4* wf = (uint4*)sm;
    const int tid = threadIdx.x;

    // ---- stage weights (bf16 hi/lo frag-ordered) + biases ----
    stage_w(wf + WF_L1, dw1, 2, 8, 64, tid);
    stage_w(wf + WF_L2, dw2, 4, 2, 16, tid);
    stage_w(wf + WF_C1, cw1, 2, 8, 64, tid);
    stage_w(wf + WF_C2, cw2, 4, 8, 64, tid);
    stage_w(wf + WF_C3, cw3, 4, 8, 64, tid);
    stage_w(wf + WF_C4, cw4, 4, 1,  3, tid);
    for (int i = tid; i < 64; i += THREADS) sm[BIAS_F + i] = db1[i];
    for (int i = tid; i < 16; i += THREADS) sm[BIAS_F + 64 + i] = db2[i];
    for (int i = tid; i < 64; i += THREADS) sm[BIAS_F + 80 + i] = cb1[i];
    for (int i = tid; i < 64; i += THREADS) sm[BIAS_F + 144 + i] = cb2[i];
    for (int i = tid; i < 64; i += THREADS) sm[BIAS_F + 208 + i] = cb3[i];
    for (int i = tid; i < 8;  i += THREADS) sm[BIAS_F + 272 + i] = (i < 3) ? cb4[i] : 0.f;
    __syncthreads();

    const int lane = tid & 31, warp = tid >> 5;
    float* Aw = sm + STG_F + warp * (32 * RS);

    const float RESV[16] = {16.f, 20.f, 25.f, 32.f, 40.f, 50.f, 64.f, 80.f,
                            101.f, 128.f, 161.f, 203.f, 256.f, 322.f, 406.f, 512.f};

    for (int wt = blockIdx.x * NWARP + warp; wt < NWTILES; wt += NCTA * NWARP) {
        const int p = wt * 32 + lane;

        // ---------- hash-grid encode (1 point per lane) ----------
        const float cx = coords[3 * p + 0];
        const float cy = coords[3 * p + 1];
        const float cz = coords[3 * p + 2];
        float dxr = dirs[3 * p + 0];
        float dyr = dirs[3 * p + 1];
        float dzr = dirs[3 * p + 2];

        float feat[32];
#pragma unroll
        for (int l = 0; l < 16; l++) {
            const float r = RESV[l];
            float fx = cx * r, fy = cy * r, fz = cz * r;
            float xf = floorf(fx), yf = floorf(fy), zf = floorf(fz);
            float tx = fx - xf, ty = fy - yf, tz = fz - zf;
            uint32_t px = (uint32_t)xf, py = (uint32_t)yf, pz = (uint32_t)zf;
            uint32_t hx0 = px,                hx1 = px + 1u;
            uint32_t hy0 = py * 2654435761u,  hy1 = hy0 + 2654435761u;
            uint32_t hz0 = pz * 805459861u,   hz1 = hz0 + 805459861u;
            const u64* tt = emb + ((size_t)l << 19);
            u64 e000 = __ldg(tt + ((hx0 ^ hy0 ^ hz0) & TMASK));
            u64 e001 = __ldg(tt + ((hx0 ^ hy0 ^ hz1) & TMASK));
            u64 e010 = __ldg(tt + ((hx0 ^ hy1 ^ hz0) & TMASK));
            u64 e011 = __ldg(tt + ((hx0 ^ hy1 ^ hz1) & TMASK));
            u64 e100 = __ldg(tt + ((hx1 ^ hy0 ^ hz0) & TMASK));
            u64 e101 = __ldg(tt + ((hx1 ^ hy0 ^ hz1) & TMASK));
            u64 e110 = __ldg(tt + ((hx1 ^ hy1 ^ hz0) & TMASK));
            u64 e111 = __ldg(tt + ((hx1 ^ hy1 ^ hz1) & TMASK));

            float ux = 1.f - tx, uy = 1.f - ty, uz = 1.f - tz;
            float w00 = ux * uy, w01 = ux * ty, w10 = tx * uy, w11 = tx * ty;
            float2 v; float a0 = 0.f, a1 = 0.f, w;
            w = w00 * uz; v = *(float2*)&e000; a0 = fmaf(w, v.x, a0); a1 = fmaf(w, v.y, a1);
            w = w00 * tz; v = *(float2*)&e001; a0 = fmaf(w, v.x, a0); a1 = fmaf(w, v.y, a1);
            w = w01 * uz; v = *(float2*)&e010; a0 = fmaf(w, v.x, a0); a1 = fmaf(w, v.y, a1);
            w = w01 * tz; v = *(float2*)&e011; a0 = fmaf(w, v.x, a0); a1 = fmaf(w, v.y, a1);
            w = w10 * uz; v = *(float2*)&e100; a0 = fmaf(w, v.x, a0); a1 = fmaf(w, v.y, a1);
            w = w10 * tz; v = *(float2*)&e101; a0 = fmaf(w, v.x, a0); a1 = fmaf(w, v.y, a1);
            w = w11 * uz; v = *(float2*)&e110; a0 = fmaf(w, v.x, a0); a1 = fmaf(w, v.y, a1);
            w = w11 * tz; v = *(float2*)&e111; a0 = fmaf(w, v.x, a0); a1 = fmaf(w, v.y, a1);
            feat[2 * l] = a0; feat[2 * l + 1] = a1;
        }

        // stage features (row = lane, cols 0..31)
        float* frow = Aw + lane * RS;
#pragma unroll
        for (int i = 0; i < 8; i++)
            *(float4*)(frow + 4 * i) =
                make_float4(feat[4 * i], feat[4 * i + 1], feat[4 * i + 2], feat[4 * i + 3]);
        __syncwarp();

        // ---------- density MLP ----------
        layer_relu<32, 64>(wf + WF_L1, sm + BIAS_F, Aw, lane);
        layer_l2(wf + WF_L2, sm + BIAS_F + 64, Aw, lane);

        out[p] = expf(frow[16]);

        // ---------- SH deg-4 into cols 0..15 ----------
        {
            float nrm = sqrtf(dxr * dxr + dyr * dyr + dzr * dzr);
            float x = dxr / nrm, y = dyr / nrm, z = dzr / nrm;
            x = ((x + 1.f) * 0.5f) * 2.f - 1.f;
            y = ((y + 1.f) * 0.5f) * 2.f - 1.f;
            z = ((z + 1.f) * 0.5f) * 2.f - 1.f;
            float xx = x * x, yy = y * y, zz = z * z;
            float xy = x * y, yz = y * z, xz = x * z;
            *(float4*)(frow + 0) = make_float4(
                0.28209479177387814f,
                -0.48860251190291987f * y,
                 0.48860251190291987f * z,
                -0.48860251190291987f * x);
            *(float4*)(frow + 4) = make_float4(
                 1.0925484305920792f * xy,
                -1.0925484305920792f * yz,
                 0.94617469575756f * zz - 0.31539156525252f,
                -1.0925484305920792f * xz);
            *(float4*)(frow + 8) = make_float4(
                 0.5462742152960396f * (xx - yy),
                 0.5900435899266435f * y * (-3.0f * xx + yy),
                 2.890611442640554f * xy * z,
                 0.4570457994644657f * y * (1.0f - 5.0f * zz));
            *(float4*)(frow + 12) = make_float4(
                 0.3731763325901154f * z * (5.0f * zz - 3.0f),
                 0.4570457994644657f * x * (1.0f - 5.0f * zz),
                 1.445305721320277f * z * (xx - yy),
                 0.5900435899266435f * x * (xx - 3.0f * yy));
        }
        __syncwarp();

        // ---------- color MLP ----------
        layer_relu<32, 64>(wf + WF_C1, sm + BIAS_F + 80,  Aw, lane);
        layer_relu<64, 64>(wf + WF_C2, sm + BIAS_F + 144, Aw, lane);
        layer_relu<64, 64>(wf + WF_C3, sm + BIAS_F + 208, Aw, lane);
        layer_c4(wf + WF_C4, sm + BIAS_F + 272, Aw, lane, out, wt * 32);
    }
}

extern "C" void kernel_launch(void* const* d_in, const int* in_sizes, int n_in,
                              void* d_out, int out_size)
{
    const float* coords = (const float*)d_in[0];
    const float* dirs   = (const float*)d_in[1];
    const u64*   emb    = (const u64*)d_in[2];
    const float* dw1 = (const float*)d_in[3];
    const float* db1 = (const float*)d_in[4];
    const float* dw2 = (const float*)d_in[5];
    const float* db2 = (const float*)d_in[6];
    const float* cw1 = (const float*)d_in[7];
    const float* cb1 = (const float*)d_in[8];
    const float* cw2 = (const float*)d_in[9];
    const float* cb2 = (const float*)d_in[10];
    const float* cw3 = (const float*)d_in[11];
    const float* cb3 = (const float*)d_in[12];
    const float* cw4 = (const float*)d_in[13];
    const float* cb4 = (const float*)d_in[14];
    float* out = (float*)d_out;

    cudaFuncSetAttribute(nerf_mma_kernel,
                         cudaFuncAttributeMaxDynamicSharedMemorySize, SMEM_BYTES);

    nerf_mma_kernel<<<NCTA, THREADS, SMEM_BYTES>>>(
        coords, dirs, emb,
        dw1, db1, dw2, db2,
        cw1, cb1, cw2, cb2, cw3, cb3, cw4, cb4,
        out);
}